// round 7
// baseline (speedup 1.0000x reference)
#include <cuda_runtime.h>
#include <cuda_fp16.h>
#include <cstdint>

// Problem constants (fixed dataset)
#define N_NODES 16384
#define EMB     500
#define EMBP    512
#define IN_SZ   4096
#define MAX_E   524288
#define NMASK   (N_NODES - 1)

// ---------------- scratch (device globals) ----------------------------------
__device__ __align__(16) __half g_xh[(size_t)N_NODES * IN_SZ];
__device__ __align__(16) __half g_wench[EMBP * IN_SZ];
__device__ __align__(16) float  g_bencp[EMBP];
__device__ __align__(16) __half g_wdech[IN_SZ * EMBP];
__device__ __align__(16) __half g_hh[N_NODES * EMBP];
__device__ __align__(16) __half g_hgch[N_NODES * EMBP];
__device__ float g_dinv[N_NODES];
__device__ int   g_deg[N_NODES];
__device__ int   g_count[N_NODES];
__device__ int   g_off[N_NODES + 1];
__device__ int   g_cursor[N_NODES];
__device__ int   g_src[MAX_E];

// ---------------- conversion prologue ---------------------------------------
__global__ void conv_x_kernel(const float4* __restrict__ x) {
    size_t i = (size_t)blockIdx.x * blockDim.x + threadIdx.x;
    float4 v = x[i];
    __half2* d = (__half2*)g_xh;
    d[i * 2]     = __floats2half2_rn(v.x, v.y);
    d[i * 2 + 1] = __floats2half2_rn(v.z, v.w);
}

__global__ void conv_wenc_kernel(const float* __restrict__ wenc) {
    int q = blockIdx.x * blockDim.x + threadIdx.x;
    int row = q >> 10;
    int c4 = (q & 1023) * 4;
    __half2 h0, h1;
    if (row < EMB) {
        float4 v = *(const float4*)(wenc + (size_t)row * IN_SZ + c4);
        h0 = __floats2half2_rn(v.x, v.y);
        h1 = __floats2half2_rn(v.z, v.w);
    } else {
        h0 = __floats2half2_rn(0.f, 0.f);
        h1 = h0;
    }
    __half2* d = (__half2*)(g_wench + (size_t)row * IN_SZ + c4);
    d[0] = h0; d[1] = h1;
}

__global__ void conv_benc_kernel(const float* __restrict__ benc) {
    int i = blockIdx.x * blockDim.x + threadIdx.x;
    if (i < EMBP) g_bencp[i] = (i < EMB) ? benc[i] : 0.f;
}

__global__ void conv_wdec_kernel(const float* __restrict__ wdec) {
    int q = blockIdx.x * blockDim.x + threadIdx.x;
    int row = q >> 7;
    int c = (q & 127) * 4;
    __half2 h0, h1;
    if (c < EMB) {
        float4 v = *(const float4*)(wdec + (size_t)row * EMB + c);
        h0 = __floats2half2_rn(v.x, v.y);
        h1 = __floats2half2_rn(v.z, v.w);
    } else {
        h0 = __floats2half2_rn(0.f, 0.f);
        h1 = h0;
    }
    __half2* d = (__half2*)(g_wdech + (size_t)row * EMBP + c);
    d[0] = h0; d[1] = h1;
}

// ---------------- CSR build --------------------------------------------------
__global__ void zero_kernel() {
    int i = blockIdx.x * blockDim.x + threadIdx.x;
    if (i < 2 * N_NODES) {
        if (i < N_NODES) g_deg[i] = 0;
        else             g_count[i - N_NODES] = 0;
    }
}

__global__ void count_kernel(const int* __restrict__ ei, int E) {
    int e = blockIdx.x * blockDim.x + threadIdx.x;
    if (e < E) {
        atomicAdd(&g_deg[ei[e] & NMASK], 1);
        atomicAdd(&g_count[ei[E + e] & NMASK], 1);
    }
}

__global__ void dinv_kernel() {
    int i = blockIdx.x * blockDim.x + threadIdx.x;
    if (i < N_NODES) {
        int d = g_deg[i];
        g_dinv[i] = (d > 0) ? rsqrtf((float)d) : 0.0f;
    }
}

__global__ void scan_kernel() {
    __shared__ int sdata[1024];
    int t = threadIdx.x;
    int local[16];
    int sum = 0;
#pragma unroll
    for (int i = 0; i < 16; i++) {
        local[i] = sum;
        sum += g_count[t * 16 + i];
    }
    sdata[t] = sum;
    __syncthreads();
    for (int off = 1; off < 1024; off <<= 1) {
        int v = 0;
        if (t >= off) v = sdata[t - off];
        __syncthreads();
        if (t >= off) sdata[t] += v;
        __syncthreads();
    }
    int base = sdata[t] - sum;
#pragma unroll
    for (int i = 0; i < 16; i++) {
        int o = base + local[i];
        g_off[t * 16 + i] = o;
        g_cursor[t * 16 + i] = o;
    }
    if (t == 1023) g_off[N_NODES] = base + sum;
}

__global__ void fill_kernel(const int* __restrict__ ei, int E) {
    int e = blockIdx.x * blockDim.x + threadIdx.x;
    if (e < E) {
        int col = ei[E + e] & NMASK;
        int slot = atomicAdd(&g_cursor[col], 1);
        g_src[slot < MAX_E ? slot : MAX_E - 1] = ei[e] & NMASK;
    }
}

// ---------------- GCN aggregate ----------------------------------------------
__global__ __launch_bounds__(128)
void aggregate_kernel(const float* __restrict__ conv_weight) {
    int n = blockIdx.x;
    int t = threadIdx.x;
    float cw = conv_weight[0];
    float dn = g_dinv[n];
    int beg = g_off[n], end = g_off[n + 1];
    float a0 = 0.f, a1 = 0.f, a2 = 0.f, a3 = 0.f;
    for (int e = beg; e < end; e++) {
        int s = g_src[e];
        float coef = dn * g_dinv[s] * cw;
        uint2 r = *(const uint2*)(g_hh + (size_t)s * EMBP + t * 4);
        __half2 h0 = *(__half2*)&r.x, h1 = *(__half2*)&r.y;
        float2 p0 = __half22float2(h0), p1 = __half22float2(h1);
        a0 += coef * p0.x; a1 += coef * p0.y;
        a2 += coef * p1.x; a3 += coef * p1.y;
    }
    uint2 rs = *(const uint2*)(g_hh + (size_t)n * EMBP + t * 4);
    __half2 s0 = *(__half2*)&rs.x, s1 = *(__half2*)&rs.y;
    float2 q0 = __half22float2(s0), q1 = __half22float2(s1);
    __half2 o0 = __floats2half2_rn(a0 + q0.x, a1 + q0.y);
    __half2 o1 = __floats2half2_rn(a2 + q1.x, a3 + q1.y);
    uint2 w;
    w.x = *(uint32_t*)&o0; w.y = *(uint32_t*)&o1;
    *(uint2*)(g_hgch + (size_t)n * EMBP + t * 4) = w;
}

// ---------------- fp16 mma.sync GEMM: 128x256 tile, ldmatrix, 3-stage -------
__device__ __forceinline__ void mma16816(float* c, const uint32_t* a, uint32_t b0, uint32_t b1) {
    asm volatile(
        "mma.sync.aligned.m16n8k16.row.col.f32.f16.f16.f32 "
        "{%0,%1,%2,%3}, {%4,%5,%6,%7}, {%8,%9}, {%0,%1,%2,%3};\n"
        : "+f"(c[0]), "+f"(c[1]), "+f"(c[2]), "+f"(c[3])
        : "r"(a[0]), "r"(a[1]), "r"(a[2]), "r"(a[3]), "r"(b0), "r"(b1));
}

__device__ __forceinline__ void ldsm4(uint32_t* r, uint32_t addr) {
    asm volatile("ldmatrix.sync.aligned.m8n8.x4.shared.b16 {%0,%1,%2,%3}, [%4];\n"
        : "=r"(r[0]), "=r"(r[1]), "=r"(r[2]), "=r"(r[3]) : "r"(addr));
}

__device__ __forceinline__ void cpasync16(uint32_t dst, const void* src) {
    asm volatile("cp.async.cg.shared.global [%0], [%1], 16;\n" :: "r"(dst), "l"(src));
}

// tile geometry: CTA 128(m) x 256(n), BK=32, 8 warps as 2(m) x 4(n), warp 64x64
#define A_STG    10240            // 128 rows x 80 B
#define B_STG    20480            // 256 rows x 80 B
#define STAGE_SZ (A_STG + B_STG)  // 30720
#define SMEM_GEMM (3 * STAGE_SZ)  // 92160

// PHASE 0: encode  g_hh = sigmoid(g_xh @ g_wench^T + g_bencp)  [16384x512], K=4096
// PHASE 1: decode  out  = g_hgch @ g_wdech^T + bdec            [16384x4096], K=512
template <int PHASE>
__global__ __launch_bounds__(256, 1)
void gemm_async(const float* __restrict__ bias_in, float* __restrict__ Cout) {
    constexpr int K   = (PHASE == 0) ? IN_SZ : EMBP;
    constexpr int LDA = (PHASE == 0) ? IN_SZ : EMBP;
    constexpr int LDB = (PHASE == 0) ? IN_SZ : EMBP;
    constexpr int LDC = (PHASE == 0) ? EMBP  : IN_SZ;
    constexpr int NC  = K / 32;
    const __half* A = (PHASE == 0) ? g_xh    : g_hgch;
    const __half* B = (PHASE == 0) ? g_wench : g_wdech;
    const float* bias = (PHASE == 0) ? g_bencp : bias_in;

    extern __shared__ __align__(16) char smem[];
    uint32_t sbase;
    asm("{ .reg .u64 t; cvta.to.shared.u64 t, %1; cvt.u32.u64 %0, t; }" : "=r"(sbase) : "l"(smem));

    int tid = threadIdx.x;
    int m0 = blockIdx.y * 128;
    int n0 = blockIdx.x * 256;
    int lane = tid & 31, wid = tid >> 5;
    int wm = wid & 1, wn = wid >> 1;   // 2x4 warps; warp tile 64(m) x 64(n)

    // cp.async chunk coords: stage = A(512 chunks) + B(1024 chunks), 6/thread
    // A chunks: idx = row*4 + c (c=0..3), B chunks: idx = row*4 + c
    int ar0 = tid >> 2,         ac0 = tid & 3;           // A chunks 0..255
    int ar1 = (tid + 256) >> 2, ac1 = (tid + 256) & 3;   // A chunks 256..511
    int br0 = tid >> 2,         bc0 = tid & 3;           // B chunks 0..255
    int br1 = (tid + 256) >> 2, bc1 = (tid + 256) & 3;
    int br2 = (tid + 512) >> 2, bc2 = (tid + 512) & 3;
    int br3 = (tid + 768) >> 2, bc3 = (tid + 768) & 3;

    // ldmatrix per-thread offsets
    int quad = lane >> 3, rin = lane & 7;
    uint32_t offA = (uint32_t)((wm * 64 + (quad & 1) * 8 + rin) * 80 + (quad >> 1) * 16);
    uint32_t offB = (uint32_t)((wn * 64 + ((lane >> 4) & 1) * 8 + rin) * 80 + ((lane >> 3) & 1) * 16);

    float acc[4][8][4];
#pragma unroll
    for (int mt = 0; mt < 4; mt++)
#pragma unroll
        for (int nt = 0; nt < 8; nt++)
#pragma unroll
            for (int i = 0; i < 4; i++) acc[mt][nt][i] = 0.f;

    auto load_stage = [&](int st, int k0) {
        uint32_t ba = sbase + st * STAGE_SZ;
        uint32_t bb = ba + A_STG;
        cpasync16(ba + ar0 * 80 + ac0 * 16, A + (size_t)(m0 + ar0) * LDA + k0 + ac0 * 8);
        cpasync16(ba + ar1 * 80 + ac1 * 16, A + (size_t)(m0 + ar1) * LDA + k0 + ac1 * 8);
        cpasync16(bb + br0 * 80 + bc0 * 16, B + (size_t)(n0 + br0) * LDB + k0 + bc0 * 8);
        cpasync16(bb + br1 * 80 + bc1 * 16, B + (size_t)(n0 + br1) * LDB + k0 + bc1 * 8);
        cpasync16(bb + br2 * 80 + bc2 * 16, B + (size_t)(n0 + br2) * LDB + k0 + bc2 * 8);
        cpasync16(bb + br3 * 80 + bc3 * 16, B + (size_t)(n0 + br3) * LDB + k0 + bc3 * 8);
    };

    load_stage(0, 0);
    asm volatile("cp.async.commit_group;\n");
    if (NC > 1) {
        load_stage(1, 32);
        asm volatile("cp.async.commit_group;\n");
    }

    for (int i = 0; i < NC; i++) {
        if (i + 2 < NC) {
            load_stage((i + 2) % 3, (i + 2) * 32);
            asm volatile("cp.async.commit_group;\n");
            asm volatile("cp.async.wait_group 2;\n");
        } else if (i + 1 < NC) {
            asm volatile("cp.async.wait_group 1;\n");
        } else {
            asm volatile("cp.async.wait_group 0;\n");
        }
        __syncthreads();

        uint32_t baseA = sbase + (i % 3) * STAGE_SZ + offA;
        uint32_t baseB = sbase + (i % 3) * STAGE_SZ + A_STG + offB;
#pragma unroll
        for (int ks = 0; ks < 32; ks += 16) {
            uint32_t af[4][4], bf[4][4];
#pragma unroll
            for (int mt = 0; mt < 4; mt++)
                ldsm4(af[mt], baseA + mt * (16 * 80) + ks * 2);
#pragma unroll
            for (int ntp = 0; ntp < 4; ntp++)
                ldsm4(bf[ntp], baseB + ntp * (16 * 80) + ks * 2);
#pragma unroll
            for (int mt = 0; mt < 4; mt++) {
#pragma unroll
                for (int nt = 0; nt < 8; nt++)
                    mma16816(acc[mt][nt], af[mt], bf[nt >> 1][(nt & 1) * 2], bf[nt >> 1][(nt & 1) * 2 + 1]);
            }
        }
        __syncthreads();
    }

    // epilogue
    int g = lane >> 2, c = lane & 3;
#pragma unroll
    for (int mt = 0; mt < 4; mt++) {
#pragma unroll
        for (int nt = 0; nt < 8; nt++) {
            int n = n0 + wn * 64 + nt * 8 + c * 2;
            float b0 = bias[n], b1 = bias[n + 1];
#pragma unroll
            for (int hr = 0; hr < 2; hr++) {
                int m = m0 + wm * 64 + mt * 16 + g + hr * 8;
                float v0 = acc[mt][nt][hr * 2 + 0] + b0;
                float v1 = acc[mt][nt][hr * 2 + 1] + b1;
                if (PHASE == 0) {
                    v0 = 1.0f / (1.0f + __expf(-v0));
                    v1 = 1.0f / (1.0f + __expf(-v1));
                    *(__half2*)(g_hh + (size_t)m * LDC + n) = __floats2half2_rn(v0, v1);
                } else {
                    *(float2*)(Cout + (size_t)m * LDC + n) = make_float2(v0, v1);
                }
            }
        }
    }
}

// ---------------- launch ----------------------------------------------------
extern "C" void kernel_launch(void* const* d_in, const int* in_sizes, int n_in,
                              void* d_out, int out_size) {
    const float* x    = (const float*)d_in[0];
    const int*   ei   = (const int*)d_in[1];
    const float* wenc = (const float*)d_in[2];
    const float* benc = (const float*)d_in[3];
    const float* wdec = (const float*)d_in[4];
    const float* bdec = (const float*)d_in[5];
    const float* cw   = (const float*)d_in[6];
    float*       out  = (float*)d_out;

    int E = in_sizes[1] / 2;

    cudaFuncSetAttribute(gemm_async<0>, cudaFuncAttributeMaxDynamicSharedMemorySize, SMEM_GEMM);
    cudaFuncSetAttribute(gemm_async<1>, cudaFuncAttributeMaxDynamicSharedMemorySize, SMEM_GEMM);

    // operand conversion prologue
    conv_x_kernel<<<(N_NODES * (IN_SZ / 4)) / 256, 256>>>((const float4*)x);
    conv_wenc_kernel<<<(EMBP * IN_SZ / 4) / 256, 256>>>(wenc);
    conv_benc_kernel<<<2, 256>>>(benc);
    conv_wdec_kernel<<<(IN_SZ * EMBP / 4) / 256, 256>>>(wdec);

    // CSR build pipeline
    zero_kernel<<<(2 * N_NODES + 511) / 512, 512>>>();
    count_kernel<<<(E + 255) / 256, 256>>>(ei, E);
    dinv_kernel<<<(N_NODES + 511) / 512, 512>>>();
    scan_kernel<<<1, 1024>>>();
    fill_kernel<<<(E + 255) / 256, 256>>>(ei, E);

    // encode: [16384 x 512] = sigmoid(x @ wenc^T + benc), K=4096
    {
        dim3 grid(EMBP / 256, N_NODES / 128);
        gemm_async<0><<<grid, 256, SMEM_GEMM>>>(nullptr, nullptr);
    }

    // graph conv
    aggregate_kernel<<<N_NODES, 128>>>(cw);

    // decode: [16384 x 4096] = hgc @ wdec^T + bdec, K=512
    {
        dim3 grid(IN_SZ / 256, N_NODES / 128);
        gemm_async<1><<<grid, 256, SMEM_GEMM>>>(bdec, out);
    }
}

// round 8
// speedup vs baseline: 1.2206x; 1.2206x over previous
#include <cuda_runtime.h>
#include <cuda_fp16.h>
#include <cstdint>

// Problem constants (fixed dataset)
#define N_NODES 16384
#define EMB     500
#define EMBP    512
#define IN_SZ   4096
#define MAX_E   524288
#define NMASK   (N_NODES - 1)

// ---------------- scratch (device globals) ----------------------------------
__device__ __align__(16) __half g_xh[(size_t)N_NODES * IN_SZ];
__device__ __align__(16) __half g_wench[EMBP * IN_SZ];
__device__ __align__(16) float  g_bencp[EMBP];
__device__ __align__(16) __half g_wdech[IN_SZ * EMBP];
__device__ __align__(16) __half g_hh[N_NODES * EMBP];
__device__ __align__(16) __half g_hgch[N_NODES * EMBP];
__device__ float g_dinv[N_NODES];
__device__ int   g_deg[N_NODES];
__device__ int   g_count[N_NODES];
__device__ int   g_off[N_NODES + 1];
__device__ int   g_cursor[N_NODES];
__device__ int   g_src[MAX_E];

// ---------------- conversion prologue ---------------------------------------
__global__ void conv_x_kernel(const float4* __restrict__ x) {
    size_t i = (size_t)blockIdx.x * blockDim.x + threadIdx.x;
    float4 v = x[i];
    __half2* d = (__half2*)g_xh;
    d[i * 2]     = __floats2half2_rn(v.x, v.y);
    d[i * 2 + 1] = __floats2half2_rn(v.z, v.w);
}

__global__ void conv_wenc_kernel(const float* __restrict__ wenc) {
    int q = blockIdx.x * blockDim.x + threadIdx.x;
    int row = q >> 10;
    int c4 = (q & 1023) * 4;
    __half2 h0, h1;
    if (row < EMB) {
        float4 v = *(const float4*)(wenc + (size_t)row * IN_SZ + c4);
        h0 = __floats2half2_rn(v.x, v.y);
        h1 = __floats2half2_rn(v.z, v.w);
    } else {
        h0 = __floats2half2_rn(0.f, 0.f);
        h1 = h0;
    }
    __half2* d = (__half2*)(g_wench + (size_t)row * IN_SZ + c4);
    d[0] = h0; d[1] = h1;
}

__global__ void conv_benc_kernel(const float* __restrict__ benc) {
    int i = blockIdx.x * blockDim.x + threadIdx.x;
    if (i < EMBP) g_bencp[i] = (i < EMB) ? benc[i] : 0.f;
}

__global__ void conv_wdec_kernel(const float* __restrict__ wdec) {
    int q = blockIdx.x * blockDim.x + threadIdx.x;
    int row = q >> 7;
    int c = (q & 127) * 4;
    __half2 h0, h1;
    if (c < EMB) {
        float4 v = *(const float4*)(wdec + (size_t)row * EMB + c);
        h0 = __floats2half2_rn(v.x, v.y);
        h1 = __floats2half2_rn(v.z, v.w);
    } else {
        h0 = __floats2half2_rn(0.f, 0.f);
        h1 = h0;
    }
    __half2* d = (__half2*)(g_wdech + (size_t)row * EMBP + c);
    d[0] = h0; d[1] = h1;
}

// ---------------- CSR build --------------------------------------------------
__global__ void zero_kernel() {
    int i = blockIdx.x * blockDim.x + threadIdx.x;
    if (i < 2 * N_NODES) {
        if (i < N_NODES) g_deg[i] = 0;
        else             g_count[i - N_NODES] = 0;
    }
}

__global__ void count_kernel(const int* __restrict__ ei, int E) {
    int e = blockIdx.x * blockDim.x + threadIdx.x;
    if (e < E) {
        atomicAdd(&g_deg[ei[e] & NMASK], 1);
        atomicAdd(&g_count[ei[E + e] & NMASK], 1);
    }
}

__global__ void dinv_kernel() {
    int i = blockIdx.x * blockDim.x + threadIdx.x;
    if (i < N_NODES) {
        int d = g_deg[i];
        g_dinv[i] = (d > 0) ? rsqrtf((float)d) : 0.0f;
    }
}

__global__ void scan_kernel() {
    __shared__ int sdata[1024];
    int t = threadIdx.x;
    int local[16];
    int sum = 0;
#pragma unroll
    for (int i = 0; i < 16; i++) {
        local[i] = sum;
        sum += g_count[t * 16 + i];
    }
    sdata[t] = sum;
    __syncthreads();
    for (int off = 1; off < 1024; off <<= 1) {
        int v = 0;
        if (t >= off) v = sdata[t - off];
        __syncthreads();
        if (t >= off) sdata[t] += v;
        __syncthreads();
    }
    int base = sdata[t] - sum;
#pragma unroll
    for (int i = 0; i < 16; i++) {
        int o = base + local[i];
        g_off[t * 16 + i] = o;
        g_cursor[t * 16 + i] = o;
    }
    if (t == 1023) g_off[N_NODES] = base + sum;
}

__global__ void fill_kernel(const int* __restrict__ ei, int E) {
    int e = blockIdx.x * blockDim.x + threadIdx.x;
    if (e < E) {
        int col = ei[E + e] & NMASK;
        int slot = atomicAdd(&g_cursor[col], 1);
        g_src[slot < MAX_E ? slot : MAX_E - 1] = ei[e] & NMASK;
    }
}

// ---------------- GCN aggregate ----------------------------------------------
__global__ __launch_bounds__(128)
void aggregate_kernel(const float* __restrict__ conv_weight) {
    int n = blockIdx.x;
    int t = threadIdx.x;
    float cw = conv_weight[0];
    float dn = g_dinv[n];
    int beg = g_off[n], end = g_off[n + 1];
    float a0 = 0.f, a1 = 0.f, a2 = 0.f, a3 = 0.f;
    for (int e = beg; e < end; e++) {
        int s = g_src[e];
        float coef = dn * g_dinv[s] * cw;
        uint2 r = *(const uint2*)(g_hh + (size_t)s * EMBP + t * 4);
        __half2 h0 = *(__half2*)&r.x, h1 = *(__half2*)&r.y;
        float2 p0 = __half22float2(h0), p1 = __half22float2(h1);
        a0 += coef * p0.x; a1 += coef * p0.y;
        a2 += coef * p1.x; a3 += coef * p1.y;
    }
    uint2 rs = *(const uint2*)(g_hh + (size_t)n * EMBP + t * 4);
    __half2 s0 = *(__half2*)&rs.x, s1 = *(__half2*)&rs.y;
    float2 q0 = __half22float2(s0), q1 = __half22float2(s1);
    __half2 o0 = __floats2half2_rn(a0 + q0.x, a1 + q0.y);
    __half2 o1 = __floats2half2_rn(a2 + q1.x, a3 + q1.y);
    uint2 w;
    w.x = *(uint32_t*)&o0; w.y = *(uint32_t*)&o1;
    *(uint2*)(g_hgch + (size_t)n * EMBP + t * 4) = w;
}

// ---------------- fp16 mma.sync GEMM: 128x128 tile, 4 warps of 64x64 --------
__device__ __forceinline__ void mma16816(float* c, const uint32_t* a, uint32_t b0, uint32_t b1) {
    asm volatile(
        "mma.sync.aligned.m16n8k16.row.col.f32.f16.f16.f32 "
        "{%0,%1,%2,%3}, {%4,%5,%6,%7}, {%8,%9}, {%0,%1,%2,%3};\n"
        : "+f"(c[0]), "+f"(c[1]), "+f"(c[2]), "+f"(c[3])
        : "r"(a[0]), "r"(a[1]), "r"(a[2]), "r"(a[3]), "r"(b0), "r"(b1));
}

__device__ __forceinline__ void ldsm4(uint32_t* r, uint32_t addr) {
    asm volatile("ldmatrix.sync.aligned.m8n8.x4.shared.b16 {%0,%1,%2,%3}, [%4];\n"
        : "=r"(r[0]), "=r"(r[1]), "=r"(r[2]), "=r"(r[3]) : "r"(addr));
}

__device__ __forceinline__ void cpasync16(uint32_t dst, const void* src) {
    asm volatile("cp.async.cg.shared.global [%0], [%1], 16;\n" :: "r"(dst), "l"(src));
}

// tile geometry: CTA 128(m) x 128(n), BK=32; 4 warps as 2(m) x 2(n), warp 64x64
#define A_STG    10240            // 128 rows x 80 B
#define B_STG    10240
#define STAGE_SZ (A_STG + B_STG)  // 20480
#define SMEM_GEMM (3 * STAGE_SZ)  // 61440

// PHASE 0: encode  g_hh = sigmoid(g_xh @ g_wench^T + g_bencp)  [16384x512], K=4096
// PHASE 1: decode  out  = g_hgch @ g_wdech^T + bdec            [16384x4096], K=512
template <int PHASE>
__global__ __launch_bounds__(128, 2)
void gemm_async(const float* __restrict__ bias_in, float* __restrict__ Cout) {
    constexpr int K   = (PHASE == 0) ? IN_SZ : EMBP;
    constexpr int LDA = (PHASE == 0) ? IN_SZ : EMBP;
    constexpr int LDB = (PHASE == 0) ? IN_SZ : EMBP;
    constexpr int LDC = (PHASE == 0) ? EMBP  : IN_SZ;
    constexpr int NC  = K / 32;
    const __half* A = (PHASE == 0) ? g_xh    : g_hgch;
    const __half* B = (PHASE == 0) ? g_wench : g_wdech;
    const float* bias = (PHASE == 0) ? g_bencp : bias_in;

    extern __shared__ __align__(16) char smem[];
    uint32_t sbase;
    asm("{ .reg .u64 t; cvta.to.shared.u64 t, %1; cvt.u32.u64 %0, t; }" : "=r"(sbase) : "l"(smem));

    int tid = threadIdx.x;
    int m0 = blockIdx.y * 128;
    int n0 = blockIdx.x * 128;
    int lane = tid & 31, wid = tid >> 5;
    int wm = wid & 1, wn = wid >> 1;   // 2x2 warps; warp tile 64(m) x 64(n)

    // ldmatrix per-thread offsets
    int quad = lane >> 3, rin = lane & 7;
    uint32_t offA = (uint32_t)((wm * 64 + (quad & 1) * 8 + rin) * 80 + (quad >> 1) * 16);
    uint32_t offB = (uint32_t)((wn * 64 + ((lane >> 4) & 1) * 8 + rin) * 80 + ((lane >> 3) & 1) * 16);

    float acc[4][8][4];
#pragma unroll
    for (int mt = 0; mt < 4; mt++)
#pragma unroll
        for (int nt = 0; nt < 8; nt++)
#pragma unroll
            for (int i = 0; i < 4; i++) acc[mt][nt][i] = 0.f;

    // cp.async: 512 A chunks + 512 B chunks per stage; 8 per thread
    auto load_stage = [&](int st, int k0) {
        uint32_t ba = sbase + st * STAGE_SZ;
        uint32_t bb = ba + A_STG;
#pragma unroll
        for (int j = 0; j < 4; j++) {
            int idx = tid + j * 128;
            int r = idx >> 2, cc = idx & 3;
            cpasync16(ba + r * 80 + cc * 16, A + (size_t)(m0 + r) * LDA + k0 + cc * 8);
            cpasync16(bb + r * 80 + cc * 16, B + (size_t)(n0 + r) * LDB + k0 + cc * 8);
        }
    };

    load_stage(0, 0);
    asm volatile("cp.async.commit_group;\n");
    if (NC > 1) {
        load_stage(1, 32);
        asm volatile("cp.async.commit_group;\n");
    }

    for (int i = 0; i < NC; i++) {
        if (i + 2 < NC) {
            load_stage((i + 2) % 3, (i + 2) * 32);
            asm volatile("cp.async.commit_group;\n");
            asm volatile("cp.async.wait_group 2;\n");
        } else if (i + 1 < NC) {
            asm volatile("cp.async.wait_group 1;\n");
        } else {
            asm volatile("cp.async.wait_group 0;\n");
        }
        __syncthreads();

        uint32_t baseA = sbase + (i % 3) * STAGE_SZ + offA;
        uint32_t baseB = sbase + (i % 3) * STAGE_SZ + A_STG + offB;
#pragma unroll
        for (int ks = 0; ks < 32; ks += 16) {
            uint32_t af[4][4], bf[4][4];
#pragma unroll
            for (int mt = 0; mt < 4; mt++)
                ldsm4(af[mt], baseA + mt * (16 * 80) + ks * 2);
#pragma unroll
            for (int ntp = 0; ntp < 4; ntp++)
                ldsm4(bf[ntp], baseB + ntp * (16 * 80) + ks * 2);
#pragma unroll
            for (int mt = 0; mt < 4; mt++) {
#pragma unroll
                for (int nt = 0; nt < 8; nt++)
                    mma16816(acc[mt][nt], af[mt], bf[nt >> 1][(nt & 1) * 2], bf[nt >> 1][(nt & 1) * 2 + 1]);
            }
        }
        __syncthreads();
    }

    // epilogue
    int g = lane >> 2, c = lane & 3;
#pragma unroll
    for (int mt = 0; mt < 4; mt++) {
#pragma unroll
        for (int nt = 0; nt < 8; nt++) {
            int n = n0 + wn * 64 + nt * 8 + c * 2;
            float b0 = bias[n], b1 = bias[n + 1];
#pragma unroll
            for (int hr = 0; hr < 2; hr++) {
                int m = m0 + wm * 64 + mt * 16 + g + hr * 8;
                float v0 = acc[mt][nt][hr * 2 + 0] + b0;
                float v1 = acc[mt][nt][hr * 2 + 1] + b1;
                if (PHASE == 0) {
                    v0 = 1.0f / (1.0f + __expf(-v0));
                    v1 = 1.0f / (1.0f + __expf(-v1));
                    *(__half2*)(g_hh + (size_t)m * LDC + n) = __floats2half2_rn(v0, v1);
                } else {
                    *(float2*)(Cout + (size_t)m * LDC + n) = make_float2(v0, v1);
                }
            }
        }
    }
}

// ---------------- launch ----------------------------------------------------
extern "C" void kernel_launch(void* const* d_in, const int* in_sizes, int n_in,
                              void* d_out, int out_size) {
    const float* x    = (const float*)d_in[0];
    const int*   ei   = (const int*)d_in[1];
    const float* wenc = (const float*)d_in[2];
    const float* benc = (const float*)d_in[3];
    const float* wdec = (const float*)d_in[4];
    const float* bdec = (const float*)d_in[5];
    const float* cw   = (const float*)d_in[6];
    float*       out  = (float*)d_out;

    int E = in_sizes[1] / 2;

    cudaFuncSetAttribute(gemm_async<0>, cudaFuncAttributeMaxDynamicSharedMemorySize, SMEM_GEMM);
    cudaFuncSetAttribute(gemm_async<1>, cudaFuncAttributeMaxDynamicSharedMemorySize, SMEM_GEMM);

    // operand conversion prologue
    conv_x_kernel<<<(N_NODES * (IN_SZ / 4)) / 256, 256>>>((const float4*)x);
    conv_wenc_kernel<<<(EMBP * IN_SZ / 4) / 256, 256>>>(wenc);
    conv_benc_kernel<<<2, 256>>>(benc);
    conv_wdec_kernel<<<(IN_SZ * EMBP / 4) / 256, 256>>>(wdec);

    // CSR build pipeline
    zero_kernel<<<(2 * N_NODES + 511) / 512, 512>>>();
    count_kernel<<<(E + 255) / 256, 256>>>(ei, E);
    dinv_kernel<<<(N_NODES + 511) / 512, 512>>>();
    scan_kernel<<<1, 1024>>>();
    fill_kernel<<<(E + 255) / 256, 256>>>(ei, E);

    // encode: [16384 x 512] = sigmoid(x @ wenc^T + benc), K=4096
    {
        dim3 grid(EMBP / 128, N_NODES / 128);
        gemm_async<0><<<grid, 128, SMEM_GEMM>>>(nullptr, nullptr);
    }

    // graph conv
    aggregate_kernel<<<N_NODES, 128>>>(cw);

    // decode: [16384 x 4096] = hgc @ wdec^T + bdec, K=512
    {
        dim3 grid(IN_SZ / 128, N_NODES / 128);
        gemm_async<1><<<grid, 128, SMEM_GEMM>>>(bdec, out);
    }
}